// round 11
// baseline (speedup 1.0000x reference)
#include <cuda_runtime.h>
#include <cuda_bf16.h>
#include <cstdint>

#define HWD 12544        // 112*112
#define TOKS 100352      // 2048 windows * 49
#define QSCALE 0.17677669529663687f   // 32^-0.5

// ========================= device scratch ===================================
__device__ float g_q[(size_t)TOKS * 256];
__device__ float g_k[(size_t)TOKS * 256];
__device__ float g_v[(size_t)TOKS * 256];
__device__ __nv_bfloat16 g_xh[(size_t)TOKS * 256];   // x gathered [t][c], high
__device__ __nv_bfloat16 g_xl[(size_t)TOKS * 256];   // low
__device__ __nv_bfloat16 g_ath[(size_t)TOKS * 256];  // attn out [t][c], high
__device__ __nv_bfloat16 g_atl[(size_t)TOKS * 256];  // low
__device__ __nv_bfloat16 g_wqkvT_h[768 * 256];       // [n][k]
__device__ __nv_bfloat16 g_wqkvT_l[768 * 256];
__device__ __nv_bfloat16 g_wprojT_h[256 * 256];
__device__ __nv_bfloat16 g_wprojT_l[256 * 256];

__device__ __forceinline__ void split_bf16(float v, __nv_bfloat16& h, __nv_bfloat16& l) {
    h = __float2bfloat16(v);
    l = __float2bfloat16(v - __bfloat162float(h));
}

// mma.sync m16n8k16 bf16 (base ISA, sm_80+)
__device__ __forceinline__ void mma16816(
    float* d, const uint32_t* a, const uint32_t* b)
{
    asm volatile(
        "mma.sync.aligned.m16n8k16.row.col.f32.bf16.bf16.f32 "
        "{%0,%1,%2,%3}, {%4,%5,%6,%7}, {%8,%9}, {%0,%1,%2,%3};"
        : "+f"(d[0]), "+f"(d[1]), "+f"(d[2]), "+f"(d[3])
        : "r"(a[0]), "r"(a[1]), "r"(a[2]), "r"(a[3]), "r"(b[0]), "r"(b[1]));
}

__device__ __forceinline__ void ldsm4(uint32_t* r, const void* p) {
    uint32_t a = (uint32_t)__cvta_generic_to_shared(p);
    asm volatile("ldmatrix.sync.aligned.m8n8.x4.shared.b16 {%0,%1,%2,%3}, [%4];"
                 : "=r"(r[0]), "=r"(r[1]), "=r"(r[2]), "=r"(r[3]) : "r"(a));
}

__device__ __forceinline__ void cp16(void* dst, const void* src) {
    uint32_t d = (uint32_t)__cvta_generic_to_shared(dst);
    asm volatile("cp.async.ca.shared.global [%0], [%1], 16;" :: "r"(d), "l"(src));
}
#define CP_COMMIT() asm volatile("cp.async.commit_group;" ::: "memory")
#define CP_WAIT1()  asm volatile("cp.async.wait_group 1;" ::: "memory")
#define CP_WAIT0()  asm volatile("cp.async.wait_group 0;" ::: "memory")

#define KPAD 40            // bf16 per smem row; 80B stride: LDSM-phase conflict-free
#define PL (128 * KPAD)    // plane elems
#define SMEM_DYN (2 * 4 * PL * 2)   // 2 bufs x 4 planes x PL bf16 = 81920 B

// ========================= k0: weight transpose + split =====================
__global__ void k0_wqkv(const float* __restrict__ w) {
    int idx = blockIdx.x * 256 + threadIdx.x;
    int k = idx / 768, n = idx % 768;
    __nv_bfloat16 h, l; split_bf16(w[idx], h, l);
    g_wqkvT_h[n * 256 + k] = h;
    g_wqkvT_l[n * 256 + k] = l;
}
__global__ void k0_wproj(const float* __restrict__ w) {
    int idx = blockIdx.x * 256 + threadIdx.x;
    int k = idx >> 8, n = idx & 255;
    __nv_bfloat16 h, l; split_bf16(w[idx], h, l);
    g_wprojT_h[n * 256 + k] = h;
    g_wprojT_l[n * 256 + k] = l;
}

// ========================= k0x: gather + split x -> [t][c] h/l planes =======
__global__ __launch_bounds__(256) void k0x(const float* __restrict__ x)
{
    __shared__ __nv_bfloat16 sh[32 * 266], sl[32 * 266];
    __shared__ int boff[32];
    const int tid = threadIdx.x;
    const int t0 = blockIdx.x * 32;
    if (tid < 32) {
        int t = t0 + tid;
        int win = t / 49, n = t - win * 49;
        int b = win >> 8, rem = win & 255;
        boff[tid] = b * (256 * HWD) + ((rem >> 4) * 7 + n / 7) * 112 + (rem & 15) * 7 + n % 7;
    }
    __syncthreads();
    {
        int t = tid & 31, c0 = tid >> 5;
        int bo = boff[t];
        #pragma unroll
        for (int it = 0; it < 32; it++) {
            int c = c0 + it * 8;
            float v = __ldg(&x[(size_t)bo + (size_t)c * HWD]);
            __nv_bfloat16 h, l; split_bf16(v, h, l);
            sh[t * 266 + c] = h;
            sl[t * 266 + c] = l;
        }
    }
    __syncthreads();
    #pragma unroll
    for (int i = 0; i < 16; i++) {
        int idx = tid + i * 256;            // 0..4095
        int tt = idx >> 7, cp2 = idx & 127; // channel pair
        uint32_t hv = *(uint32_t*)&sh[tt * 266 + cp2 * 2];
        uint32_t lv = *(uint32_t*)&sl[tt * 266 + cp2 * 2];
        *(uint32_t*)&g_xh[(size_t)(t0 + tt) * 256 + cp2 * 2] = hv;
        *(uint32_t*)&g_xl[(size_t)(t0 + tt) * 256 + cp2 * 2] = lv;
    }
}

// ========================= shared GEMM mainloop core ========================
// Per k-step: ldmatrix.x4 fragments + term-major mma issue (4-way acc ILP).
#define GEMM_KSTEP(Ah, Al, Bh, Bl, kb)                                          \
    do {                                                                        \
        uint32_t bfh[2][4], bfl[2][4];                                          \
        int brow = (lane & 7) + ((lane >> 3) & 1) * 8;                          \
        int bk = (kb) + (lane >> 4) * 8;                                        \
        _Pragma("unroll")                                                       \
        for (int p = 0; p < 2; p++) {                                           \
            ldsm4(bfh[p], &(Bh)[(wn * 32 + p * 16 + brow) * KPAD + bk]);        \
            ldsm4(bfl[p], &(Bl)[(wn * 32 + p * 16 + brow) * KPAD + bk]);        \
        }                                                                       \
        int arow = lane & 15;                                                   \
        _Pragma("unroll")                                                       \
        for (int mt = 0; mt < 4; mt++) {                                        \
            uint32_t ah[4], al[4];                                              \
            ldsm4(ah, &(Ah)[(wm * 64 + mt * 16 + arow) * KPAD + bk]);           \
            ldsm4(al, &(Al)[(wm * 64 + mt * 16 + arow) * KPAD + bk]);           \
            _Pragma("unroll")                                                   \
            for (int nt = 0; nt < 4; nt++) {                                    \
                uint32_t bb[2] = { bfh[nt >> 1][nt & 1], bfh[nt >> 1][(nt & 1) + 2] }; \
                mma16816(acc[mt][nt], ah, bb);                                  \
            }                                                                   \
            _Pragma("unroll")                                                   \
            for (int nt = 0; nt < 4; nt++) {                                    \
                uint32_t bb[2] = { bfl[nt >> 1][nt & 1], bfl[nt >> 1][(nt & 1) + 2] }; \
                mma16816(acc[mt][nt], ah, bb);                                  \
            }                                                                   \
            _Pragma("unroll")                                                   \
            for (int nt = 0; nt < 4; nt++) {                                    \
                uint32_t bb[2] = { bfh[nt >> 1][nt & 1], bfh[nt >> 1][(nt & 1) + 2] }; \
                mma16816(acc[mt][nt], al, bb);                                  \
            }                                                                   \
        }                                                                       \
    } while (0)

// Note: ldmatrix A addressing uses bk for both k-blocks since (lane>>4)*8
// selects the k8-15 matrices; arow = lane&15 selects rows within both.

// ========================= k1: QKV GEMM, cp.async + ldmatrix ================
__device__ __forceinline__ void k1_load_chunk(
    __nv_bfloat16* dsm, int buf, int cc, int tid, int t0, int n0g)
{
    const int kc = cc * 32;
    __nv_bfloat16* bb = dsm + buf * 4 * PL;
    #pragma unroll
    for (int i = 0; i < 4; i++) {
        int idx = tid + i * 256;            // A: 0..1023
        int m = idx >> 3, sub = idx & 7, pl = sub >> 2, c4 = sub & 3;
        const __nv_bfloat16* src = (pl ? g_xl : g_xh) + (size_t)(t0 + m) * 256 + kc + c4 * 8;
        cp16(bb + pl * PL + m * KPAD + c4 * 8, src);
    }
    #pragma unroll
    for (int i = 0; i < 4; i++) {
        int idx = tid + i * 256;            // B: 0..1023
        int n = idx >> 3, sub = idx & 7, pl = sub >> 2, c4 = sub & 3;
        const __nv_bfloat16* src = (pl ? g_wqkvT_l : g_wqkvT_h) + (size_t)(n0g + n) * 256 + kc + c4 * 8;
        cp16(bb + (2 + pl) * PL + n * KPAD + c4 * 8, src);
    }
    CP_COMMIT();
}

__global__ __launch_bounds__(256, 2) void k1_qkv_mma(const float* __restrict__ bias)
{
    extern __shared__ __nv_bfloat16 dsm[];
    const int tid = threadIdx.x;
    const int wid = tid >> 5, lane = tid & 31;
    const int wm = wid >> 2, wn = wid & 3;
    const int lr = lane >> 2, lc = (lane & 3) * 2;
    const int t0 = blockIdx.x * 128;
    const int n0g = blockIdx.y * 128;

    float acc[4][4][4];
    #pragma unroll
    for (int mt = 0; mt < 4; mt++)
        #pragma unroll
        for (int nt = 0; nt < 4; nt++)
            #pragma unroll
            for (int r = 0; r < 4; r++) acc[mt][nt][r] = 0.f;

    k1_load_chunk(dsm, 0, 0, tid, t0, n0g);
    for (int cc = 0; cc < 8; cc++) {
        if (cc < 7) { k1_load_chunk(dsm, (cc + 1) & 1, cc + 1, tid, t0, n0g); CP_WAIT1(); }
        else CP_WAIT0();
        __syncthreads();
        const __nv_bfloat16* bb = dsm + (cc & 1) * 4 * PL;
        const __nv_bfloat16* Ah = bb;
        const __nv_bfloat16* Al = bb + PL;
        const __nv_bfloat16* Bh = bb + 2 * PL;
        const __nv_bfloat16* Bl = bb + 3 * PL;
        GEMM_KSTEP(Ah, Al, Bh, Bl, 0);
        GEMM_KSTEP(Ah, Al, Bh, Bl, 16);
        __syncthreads();
    }

    // Epilogue: warp's 32-col slice = one head of one of q/k/v.
    {
        int col0 = n0g + wn * 32;
        int which = col0 >> 8;
        int head = (col0 >> 5) & 7;
        float scl = (which == 0) ? QSCALE : 1.f;
        float* dst = (which == 0) ? g_q : (which == 1) ? g_k : g_v;
        #pragma unroll
        for (int nt = 0; nt < 4; nt++) {
            int dloc = nt * 8 + lc;
            float bb0 = __ldg(&bias[col0 + dloc]);
            float bb1 = __ldg(&bias[col0 + dloc + 1]);
            #pragma unroll
            for (int mt = 0; mt < 4; mt++) {
                #pragma unroll
                for (int hf = 0; hf < 2; hf++) {
                    int t = t0 + wm * 64 + mt * 16 + lr + hf * 8;
                    int win = t / 49, n = t - win * 49;
                    size_t off = ((size_t)(win * 8 + head) * 49 + n) * 32 + dloc;
                    float2 v;
                    v.x = (acc[mt][nt][hf * 2 + 0] + bb0) * scl;
                    v.y = (acc[mt][nt][hf * 2 + 1] + bb1) * scl;
                    *(float2*)&dst[off] = v;
                }
            }
        }
    }
}

// ========================= k2: per-(window,head) attention (fp32) ===========
__global__ __launch_bounds__(256) void k2_attn(const float* __restrict__ rpb)
{
    __shared__ float bufA[3584];        // qs[d][n]@56 | ks at +1792 ; later PT[m][n]@52
    __shared__ float vs[49][34];
    __shared__ float Ss[56][51];        // scores; later Os[d][n]@53
    const int tid  = threadIdx.x;
    const int wh   = blockIdx.x;
    const int head = wh & 7;
    const int win  = wh >> 3;
    const size_t base = (size_t)wh * 1568;
    float* qsp = bufA;
    float* ksp = bufA + 1792;

    for (int idx = tid; idx < 1568; idx += 256) {
        int n = idx >> 5, d = idx & 31;
        qsp[d * 56 + n] = g_q[base + idx];
        ksp[d * 56 + n] = g_k[base + idx];
        vs[n][d] = g_v[base + idx];
    }
    __syncthreads();

    if (tid < 196) {
        int tyy = tid / 14, txx = tid - tyy * 14;
        int nb = tyy * 4, mb = txx * 4;
        float s[4][4];
        #pragma unroll
        for (int i = 0; i < 4; i++)
            #pragma unroll
            for (int j = 0; j < 4; j++) s[i][j] = 0.f;
        #pragma unroll
        for (int kk = 0; kk < 32; kk++) {
            float4 qq = *(const float4*)(qsp + kk * 56 + nb);
            float4 kf = *(const float4*)(ksp + kk * 56 + mb);
            const float* qa = &qq.x;
            const float* ka = &kf.x;
            #pragma unroll
            for (int i = 0; i < 4; i++)
                #pragma unroll
                for (int j = 0; j < 4; j++) s[i][j] += qa[i] * ka[j];
        }
        #pragma unroll
        for (int i = 0; i < 4; i++) {
            int n = nb + i;
            if (n < 49) {
                int in_ = n / 7, jn = n - in_ * 7;
                #pragma unroll
                for (int j = 0; j < 4; j++) {
                    int m = mb + j;
                    if (m < 49) {
                        int im = m / 7, jm = m - im * 7;
                        int ridx = (in_ - im + 6) * 13 + (jn - jm + 6);
                        Ss[n][m] = s[i][j] + rpb[ridx * 8 + head];
                    }
                }
            }
        }
    }
    __syncthreads();

    {
        int lane = tid & 31, wrp = tid >> 5;
        for (int r = wrp; r < 49; r += 8) {
            float v0 = Ss[r][lane];
            float v1 = (lane < 17) ? Ss[r][lane + 32] : -3.0e38f;
            float mx = fmaxf(v0, v1);
            #pragma unroll
            for (int o = 16; o; o >>= 1)
                mx = fmaxf(mx, __shfl_xor_sync(0xffffffffu, mx, o));
            float e0 = __expf(v0 - mx);
            float e1 = (lane < 17) ? __expf(v1 - mx) : 0.f;
            float sm = e0 + e1;
            #pragma unroll
            for (int o = 16; o; o >>= 1)
                sm += __shfl_xor_sync(0xffffffffu, sm, o);
            float inv = __fdividef(1.f, sm);
            bufA[lane * 52 + r] = e0 * inv;
            if (lane < 17) bufA[(lane + 32) * 52 + r] = e1 * inv;
        }
    }
    __syncthreads();

    float o[4][2];
    int nb2 = 0, db2 = 0;
    if (tid < 224) {
        int tyy = tid >> 4, txx = tid & 15;
        nb2 = tyy * 4; db2 = txx * 2;
        #pragma unroll
        for (int i = 0; i < 4; i++) { o[i][0] = 0.f; o[i][1] = 0.f; }
        for (int m = 0; m < 49; m++) {
            float4 p = *(const float4*)(bufA + m * 52 + nb2);
            float2 vv = *(const float2*)(&vs[m][db2]);
            const float* pa = &p.x;
            #pragma unroll
            for (int i = 0; i < 4; i++) {
                o[i][0] += pa[i] * vv.x;
                o[i][1] += pa[i] * vv.y;
            }
        }
    }
    __syncthreads();
    float* Os = &Ss[0][0];               // stride 53
    if (tid < 224) {
        #pragma unroll
        for (int j = 0; j < 2; j++)
            #pragma unroll
            for (int i = 0; i < 4; i++)
                if (nb2 + i < 49) Os[(db2 + j) * 53 + nb2 + i] = o[i][j];
    }
    __syncthreads();

    for (int e = tid; e < 1568; e += 256) {
        int nloc = e >> 5, d = e & 31;
        float v = Os[d * 53 + nloc];
        __nv_bfloat16 h, l; split_bf16(v, h, l);
        size_t gi = (size_t)(win * 49 + nloc) * 256 + head * 32 + d;
        g_ath[gi] = h;
        g_atl[gi] = l;
    }
}

// ========================= k3: projection GEMM, cp.async + ldmatrix =========
__device__ __forceinline__ void k3_load_chunk(
    __nv_bfloat16* dsm, int buf, int cc, int tid, int t0, int n0g)
{
    const int kc = cc * 32;
    __nv_bfloat16* bb = dsm + buf * 4 * PL;
    #pragma unroll
    for (int i = 0; i < 4; i++) {
        int idx = tid + i * 256;
        int m = idx >> 3, sub = idx & 7, pl = sub >> 2, c4 = sub & 3;
        const __nv_bfloat16* src = (pl ? g_atl : g_ath) + (size_t)(t0 + m) * 256 + kc + c4 * 8;
        cp16(bb + pl * PL + m * KPAD + c4 * 8, src);
    }
    #pragma unroll
    for (int i = 0; i < 4; i++) {
        int idx = tid + i * 256;
        int n = idx >> 3, sub = idx & 7, pl = sub >> 2, c4 = sub & 3;
        const __nv_bfloat16* src = (pl ? g_wprojT_l : g_wprojT_h) + (size_t)(n0g + n) * 256 + kc + c4 * 8;
        cp16(bb + (2 + pl) * PL + n * KPAD + c4 * 8, src);
    }
    CP_COMMIT();
}

__global__ __launch_bounds__(256, 2) void k3_proj_mma(
    const float* __restrict__ bias, float* __restrict__ out)
{
    extern __shared__ __nv_bfloat16 dsm[];
    __shared__ int boff[128];
    const int tid = threadIdx.x;
    const int wid = tid >> 5, lane = tid & 31;
    const int wm = wid >> 2, wn = wid & 3;
    const int lr = lane >> 2, lc = (lane & 3) * 2;
    const int t0 = blockIdx.x * 128;
    const int n0g = blockIdx.y * 128;

    if (tid < 128) {
        int t = t0 + tid;
        int win = t / 49, n = t - win * 49;
        int b = win >> 8, rem = win & 255;
        boff[tid] = b * (256 * HWD) + ((rem >> 4) * 7 + n / 7) * 112 + (rem & 15) * 7 + n % 7;
    }
    float acc[4][4][4];
    #pragma unroll
    for (int mt = 0; mt < 4; mt++)
        #pragma unroll
        for (int nt = 0; nt < 4; nt++)
            #pragma unroll
            for (int r = 0; r < 4; r++) acc[mt][nt][r] = 0.f;

    k3_load_chunk(dsm, 0, 0, tid, t0, n0g);
    for (int cc = 0; cc < 8; cc++) {
        if (cc < 7) { k3_load_chunk(dsm, (cc + 1) & 1, cc + 1, tid, t0, n0g); CP_WAIT1(); }
        else CP_WAIT0();
        __syncthreads();
        const __nv_bfloat16* bb = dsm + (cc & 1) * 4 * PL;
        const __nv_bfloat16* Ah = bb;
        const __nv_bfloat16* Al = bb + PL;
        const __nv_bfloat16* Bh = bb + 2 * PL;
        const __nv_bfloat16* Bl = bb + 3 * PL;
        GEMM_KSTEP(Ah, Al, Bh, Bl, 0);
        GEMM_KSTEP(Ah, Al, Bh, Bl, 16);
        __syncthreads();
    }

    // Epilogue: NCHW scatter
    #pragma unroll
    for (int nt = 0; nt < 4; nt++) {
        int c = n0g + wn * 32 + nt * 8 + lc;
        float bb0 = __ldg(&bias[c]);
        float bb1 = __ldg(&bias[c + 1]);
        #pragma unroll
        for (int mt = 0; mt < 4; mt++) {
            #pragma unroll
            for (int hf = 0; hf < 2; hf++) {
                int bo = boff[wm * 64 + mt * 16 + lr + hf * 8];
                out[bo + (size_t)c * HWD]       = acc[mt][nt][hf * 2 + 0] + bb0;
                out[bo + (size_t)(c + 1) * HWD] = acc[mt][nt][hf * 2 + 1] + bb1;
            }
        }
    }
}

// ---------------------------------------------------------------------------
extern "C" void kernel_launch(void* const* d_in, const int* in_sizes, int n_in,
                              void* d_out, int out_size)
{
    const float* x      = (const float*)d_in[0];
    const float* w_qkv  = (const float*)d_in[1];
    const float* b_qkv  = (const float*)d_in[2];
    const float* w_proj = (const float*)d_in[3];
    const float* b_proj = (const float*)d_in[4];
    const float* rpb    = (const float*)d_in[5];
    float* out = (float*)d_out;

    cudaFuncSetAttribute(k1_qkv_mma, cudaFuncAttributeMaxDynamicSharedMemorySize, SMEM_DYN);
    cudaFuncSetAttribute(k3_proj_mma, cudaFuncAttributeMaxDynamicSharedMemorySize, SMEM_DYN);

    k0_wqkv<<<768, 256>>>(w_qkv);
    k0_wproj<<<256, 256>>>(w_proj);
    k0x<<<3136, 256>>>(x);
    k1_qkv_mma<<<dim3(784, 6), 256, SMEM_DYN>>>(b_qkv);
    k2_attn<<<16384, 256>>>(rpb);
    k3_proj_mma<<<dim3(784, 2), 256, SMEM_DYN>>>(b_proj, out);
}

// round 12
// speedup vs baseline: 1.0298x; 1.0298x over previous
#include <cuda_runtime.h>
#include <cuda_bf16.h>
#include <cstdint>

#define HWD 12544        // 112*112
#define TOKS 100352      // 2048 windows * 49
#define NWH  16384       // 2048 windows * 8 heads
#define QSCALE 0.17677669529663687f   // 32^-0.5

// ========================= device scratch ===================================
__device__ __nv_bfloat16 g_xh[(size_t)TOKS * 256];   // x gathered [t][c], high
__device__ __nv_bfloat16 g_xl[(size_t)TOKS * 256];   // low
__device__ uint32_t g_ath32[(size_t)TOKS * 128];     // attn out [t][c] bf16 high (u32-paired)
__device__ uint32_t g_atl32[(size_t)TOKS * 128];     // low
__device__ uint32_t g_qh[(size_t)NWH * 784];         // q [wh][tok][d] bf16 pairs
__device__ uint32_t g_ql[(size_t)NWH * 784];
__device__ uint32_t g_kh[(size_t)NWH * 784];
__device__ uint32_t g_kl[(size_t)NWH * 784];
__device__ __nv_bfloat16 g_vh[(size_t)NWH * 1568];   // v TRANSPOSED [wh][d][tok]
__device__ __nv_bfloat16 g_vl[(size_t)NWH * 1568];
__device__ float g_biasfrag[8 * 4096];               // rpb bias in d-frag order per head
__device__ __nv_bfloat16 g_wqkvT_h[768 * 256];       // [n][k]
__device__ __nv_bfloat16 g_wqkvT_l[768 * 256];
__device__ __nv_bfloat16 g_wprojT_h[256 * 256];
__device__ __nv_bfloat16 g_wprojT_l[256 * 256];

__device__ __forceinline__ void split_bf16(float v, __nv_bfloat16& h, __nv_bfloat16& l) {
    h = __float2bfloat16(v);
    l = __float2bfloat16(v - __bfloat162float(h));
}
__device__ __forceinline__ uint32_t pk2(__nv_bfloat16 a, __nv_bfloat16 b) {
    __nv_bfloat162 t; t.x = a; t.y = b;
    return *(uint32_t*)&t;
}

// mma.sync m16n8k16 bf16 (base ISA, sm_80+)
__device__ __forceinline__ void mma16816(
    float* d, const uint32_t* a, const uint32_t* b)
{
    asm volatile(
        "mma.sync.aligned.m16n8k16.row.col.f32.bf16.bf16.f32 "
        "{%0,%1,%2,%3}, {%4,%5,%6,%7}, {%8,%9}, {%0,%1,%2,%3};"
        : "+f"(d[0]), "+f"(d[1]), "+f"(d[2]), "+f"(d[3])
        : "r"(a[0]), "r"(a[1]), "r"(a[2]), "r"(a[3]), "r"(b[0]), "r"(b[1]));
}

__device__ __forceinline__ void ldsm4(uint32_t* r, const void* p) {
    uint32_t a = (uint32_t)__cvta_generic_to_shared(p);
    asm volatile("ldmatrix.sync.aligned.m8n8.x4.shared.b16 {%0,%1,%2,%3}, [%4];"
                 : "=r"(r[0]), "=r"(r[1]), "=r"(r[2]), "=r"(r[3]) : "r"(a));
}

__device__ __forceinline__ void cp16(void* dst, const void* src) {
    uint32_t d = (uint32_t)__cvta_generic_to_shared(dst);
    asm volatile("cp.async.ca.shared.global [%0], [%1], 16;" :: "r"(d), "l"(src));
}
#define CP_COMMIT() asm volatile("cp.async.commit_group;" ::: "memory")
#define CP_WAIT1()  asm volatile("cp.async.wait_group 1;" ::: "memory")
#define CP_WAIT0()  asm volatile("cp.async.wait_group 0;" ::: "memory")

#define KPAD 40            // bf16 per smem row; 80B stride, conflict-free
#define PL (128 * KPAD)    // plane elems
#define SMEM_DYN (2 * 4 * PL * 2)   // 81920 B

// ========================= k0: weight transpose + split =====================
__global__ void k0_wqkv(const float* __restrict__ w) {
    int idx = blockIdx.x * 256 + threadIdx.x;
    int k = idx / 768, n = idx % 768;
    __nv_bfloat16 h, l; split_bf16(w[idx], h, l);
    g_wqkvT_h[n * 256 + k] = h;
    g_wqkvT_l[n * 256 + k] = l;
}
__global__ void k0_wproj(const float* __restrict__ w) {
    int idx = blockIdx.x * 256 + threadIdx.x;
    int k = idx >> 8, n = idx & 255;
    __nv_bfloat16 h, l; split_bf16(w[idx], h, l);
    g_wprojT_h[n * 256 + k] = h;
    g_wprojT_l[n * 256 + k] = l;
}

// ========================= k0b: rel-pos bias in fragment order ==============
// layout: g_biasfrag[head*4096 + w*1024 + lane*32 + nt*4 + cc]
//   row = 16w + (lane>>2) + (cc>=2 ? 8 : 0), col = nt*8 + (lane&3)*2 + (cc&1)
__global__ void k0b(const float* __restrict__ rpb) {
    int idx = blockIdx.x * 256 + threadIdx.x;   // < 32768
    int head = idx >> 12, e = idx & 4095;
    int w = e >> 10, r = e & 1023;
    int lane = r >> 5, v = r & 31;
    int nt = v >> 2, cc = v & 3;
    int row = 16 * w + (lane >> 2) + ((cc >= 2) ? 8 : 0);
    int col = nt * 8 + (lane & 3) * 2 + (cc & 1);
    float val;
    if (col >= 49) val = -1e30f;
    else if (row >= 49) val = 0.f;
    else {
        int in_ = row / 7, jn = row % 7, im = col / 7, jm = col % 7;
        int ri = (in_ - im + 6) * 13 + (jn - jm + 6);
        val = rpb[ri * 8 + head];
    }
    g_biasfrag[idx] = val;
}

// ========================= k0x: gather + split x -> [t][c] h/l planes =======
__global__ __launch_bounds__(256) void k0x(const float* __restrict__ x)
{
    __shared__ __nv_bfloat16 sh[32 * 266], sl[32 * 266];
    __shared__ int boff[32];
    const int tid = threadIdx.x;
    const int t0 = blockIdx.x * 32;
    if (tid < 32) {
        int t = t0 + tid;
        int win = t / 49, n = t - win * 49;
        int b = win >> 8, rem = win & 255;
        boff[tid] = b * (256 * HWD) + ((rem >> 4) * 7 + n / 7) * 112 + (rem & 15) * 7 + n % 7;
    }
    __syncthreads();
    {
        int t = tid & 31, c0 = tid >> 5;
        int bo = boff[t];
        #pragma unroll
        for (int it = 0; it < 32; it++) {
            int c = c0 + it * 8;
            float v = __ldg(&x[(size_t)bo + (size_t)c * HWD]);
            __nv_bfloat16 h, l; split_bf16(v, h, l);
            sh[t * 266 + c] = h;
            sl[t * 266 + c] = l;
        }
    }
    __syncthreads();
    #pragma unroll
    for (int i = 0; i < 16; i++) {
        int idx = tid + i * 256;
        int tt = idx >> 7, cp2 = idx & 127;
        uint32_t hv = *(uint32_t*)&sh[tt * 266 + cp2 * 2];
        uint32_t lv = *(uint32_t*)&sl[tt * 266 + cp2 * 2];
        *(uint32_t*)&g_xh[(size_t)(t0 + tt) * 256 + cp2 * 2] = hv;
        *(uint32_t*)&g_xl[(size_t)(t0 + tt) * 256 + cp2 * 2] = lv;
    }
}

// ========================= shared GEMM mainloop core ========================
#define GEMM_KSTEP(Ah, Al, Bh, Bl, kb)                                          \
    do {                                                                        \
        uint32_t bfh[2][4], bfl[2][4];                                          \
        int brow = (lane & 7) + ((lane >> 3) & 1) * 8;                          \
        int bk = (kb) + (lane >> 4) * 8;                                        \
        _Pragma("unroll")                                                       \
        for (int p = 0; p < 2; p++) {                                           \
            ldsm4(bfh[p], &(Bh)[(wn * 32 + p * 16 + brow) * KPAD + bk]);        \
            ldsm4(bfl[p], &(Bl)[(wn * 32 + p * 16 + brow) * KPAD + bk]);        \
        }                                                                       \
        int arow = lane & 15;                                                   \
        _Pragma("unroll")                                                       \
        for (int mt = 0; mt < 4; mt++) {                                        \
            uint32_t ah[4], al[4];                                              \
            ldsm4(ah, &(Ah)[(wm * 64 + mt * 16 + arow) * KPAD + bk]);           \
            ldsm4(al, &(Al)[(wm * 64 + mt * 16 + arow) * KPAD + bk]);           \
            _Pragma("unroll")                                                   \
            for (int nt = 0; nt < 4; nt++) {                                    \
                uint32_t bb[2] = { bfh[nt >> 1][nt & 1], bfh[nt >> 1][(nt & 1) + 2] }; \
                mma16816(acc[mt][nt], ah, bb);                                  \
            }                                                                   \
            _Pragma("unroll")                                                   \
            for (int nt = 0; nt < 4; nt++) {                                    \
                uint32_t bb[2] = { bfl[nt >> 1][nt & 1], bfl[nt >> 1][(nt & 1) + 2] }; \
                mma16816(acc[mt][nt], ah, bb);                                  \
            }                                                                   \
            _Pragma("unroll")                                                   \
            for (int nt = 0; nt < 4; nt++) {                                    \
                uint32_t bb[2] = { bfh[nt >> 1][nt & 1], bfh[nt >> 1][(nt & 1) + 2] }; \
                mma16816(acc[mt][nt], al, bb);                                  \
            }                                                                   \
        }                                                                       \
    } while (0)

// ========================= k1: QKV GEMM, cp.async + ldmatrix ================
__device__ __forceinline__ void k1_load_chunk(
    __nv_bfloat16* dsm, int buf, int cc, int tid, int t0, int n0g)
{
    const int kc = cc * 32;
    __nv_bfloat16* bb = dsm + buf * 4 * PL;
    #pragma unroll
    for (int i = 0; i < 4; i++) {
        int idx = tid + i * 256;
        int m = idx >> 3, sub = idx & 7, pl = sub >> 2, c4 = sub & 3;
        const __nv_bfloat16* src = (pl ? g_xl : g_xh) + (size_t)(t0 + m) * 256 + kc + c4 * 8;
        cp16(bb + pl * PL + m * KPAD + c4 * 8, src);
    }
    #pragma unroll
    for (int i = 0; i < 4; i++) {
        int idx = tid + i * 256;
        int n = idx >> 3, sub = idx & 7, pl = sub >> 2, c4 = sub & 3;
        const __nv_bfloat16* src = (pl ? g_wqkvT_l : g_wqkvT_h) + (size_t)(n0g + n) * 256 + kc + c4 * 8;
        cp16(bb + (2 + pl) * PL + n * KPAD + c4 * 8, src);
    }
    CP_COMMIT();
}

__global__ __launch_bounds__(256, 2) void k1_qkv_mma(const float* __restrict__ bias)
{
    extern __shared__ __nv_bfloat16 dsm[];
    const int tid = threadIdx.x;
    const int wid = tid >> 5, lane = tid & 31;
    const int wm = wid >> 2, wn = wid & 3;
    const int lr = lane >> 2, lc = (lane & 3) * 2;
    const int t0 = blockIdx.x * 128;
    const int n0g = blockIdx.y * 128;

    float acc[4][4][4];
    #pragma unroll
    for (int mt = 0; mt < 4; mt++)
        #pragma unroll
        for (int nt = 0; nt < 4; nt++)
            #pragma unroll
            for (int r = 0; r < 4; r++) acc[mt][nt][r] = 0.f;

    k1_load_chunk(dsm, 0, 0, tid, t0, n0g);
    for (int cc = 0; cc < 8; cc++) {
        if (cc < 7) { k1_load_chunk(dsm, (cc + 1) & 1, cc + 1, tid, t0, n0g); CP_WAIT1(); }
        else CP_WAIT0();
        __syncthreads();
        const __nv_bfloat16* bb = dsm + (cc & 1) * 4 * PL;
        GEMM_KSTEP(bb, bb + PL, bb + 2 * PL, bb + 3 * PL, 0);
        GEMM_KSTEP(bb, bb + PL, bb + 2 * PL, bb + 3 * PL, 16);
        __syncthreads();
    }

    // Epilogue: q/k -> bf16 h/l pair planes [wh][tok][d]; v transposed [wh][d][tok]
    {
        int col0 = n0g + wn * 32;
        int which = col0 >> 8;
        int head = (col0 >> 5) & 7;
        float scl = (which == 0) ? QSCALE : 1.f;
        #pragma unroll
        for (int nt = 0; nt < 4; nt++) {
            int dloc = nt * 8 + lc;
            float bb0 = __ldg(&bias[col0 + dloc]);
            float bb1 = __ldg(&bias[col0 + dloc + 1]);
            #pragma unroll
            for (int mt = 0; mt < 4; mt++) {
                #pragma unroll
                for (int hf = 0; hf < 2; hf++) {
                    int t = t0 + wm * 64 + mt * 16 + lr + hf * 8;
                    int win = t / 49, n = t - win * 49;
                    int wh = win * 8 + head;
                    float vx = (acc[mt][nt][hf * 2 + 0] + bb0) * scl;
                    float vy = (acc[mt][nt][hf * 2 + 1] + bb1) * scl;
                    __nv_bfloat16 hx, lx, hy, ly;
                    split_bf16(vx, hx, lx);
                    split_bf16(vy, hy, ly);
                    if (which < 2) {
                        uint32_t off = (uint32_t)wh * 784 + n * 16 + (dloc >> 1);
                        (which ? g_kh : g_qh)[off] = pk2(hx, hy);
                        (which ? g_kl : g_ql)[off] = pk2(lx, ly);
                    } else {
                        size_t b = (size_t)wh * 1568;
                        g_vh[b + dloc * 49 + n] = hx;
                        g_vh[b + (dloc + 1) * 49 + n] = hy;
                        g_vl[b + dloc * 49 + n] = lx;
                        g_vl[b + (dloc + 1) * 49 + n] = ly;
                    }
                }
            }
        }
    }
}

// ========================= k2: attention via mma.sync =======================
// One block per (window,head), 128 threads = 4 warps; warp w owns rows 16w..16w+15.
__global__ __launch_bounds__(128) void k2_attn()
{
    __shared__ __nv_bfloat16 sQ[2][64][40];   // [plane][tok][d]
    __shared__ __nv_bfloat16 sK[2][64][40];   // [plane][tok][d]
    __shared__ __nv_bfloat16 sV[2][32][72];   // [plane][d][tok]
    const int tid = threadIdx.x;
    const int wh = blockIdx.x;
    const int head = wh & 7, win = wh >> 3;
    const int w = tid >> 5, lane = tid & 31;
    const int lr = lane >> 2, lc = (lane & 3) * 2;

    // zero smem (pads MUST be 0: K pad rows / V pad cols would NaN-poison)
    {
        uint32_t* z1 = (uint32_t*)&sQ[0][0][0];
        uint32_t* z2 = (uint32_t*)&sK[0][0][0];
        uint32_t* z3 = (uint32_t*)&sV[0][0][0];
        for (int i = tid; i < 2560; i += 128) { z1[i] = 0; z2[i] = 0; }
        for (int i = tid; i < 1152; i += 128) z3[i] = 0;
    }
    __syncthreads();

    // load q,k (u32 pairs) and v (2B, transposed source)
    {
        const uint32_t* pq0 = g_qh + (size_t)wh * 784;
        const uint32_t* pq1 = g_ql + (size_t)wh * 784;
        const uint32_t* pk0 = g_kh + (size_t)wh * 784;
        const uint32_t* pk1 = g_kl + (size_t)wh * 784;
        for (int i = tid; i < 784; i += 128) {
            int row = i >> 4, p = i & 15;
            *(uint32_t*)&sQ[0][row][p * 2] = __ldg(&pq0[i]);
            *(uint32_t*)&sQ[1][row][p * 2] = __ldg(&pq1[i]);
            *(uint32_t*)&sK[0][row][p * 2] = __ldg(&pk0[i]);
            *(uint32_t*)&sK[1][row][p * 2] = __ldg(&pk1[i]);
        }
        const __nv_bfloat16* pv0 = g_vh + (size_t)wh * 1568;
        const __nv_bfloat16* pv1 = g_vl + (size_t)wh * 1568;
        for (int i = tid; i < 1568; i += 128) {
            int d = i / 49, t = i - d * 49;
            sV[0][d][t] = __ldg(&pv0[i]);
            sV[1][d][t] = __ldg(&pv1[i]);
        }
    }
    __syncthreads();

    // ---- S = q k^T (3-term) over M=16/warp, N=64, K=32 ----
    float sacc[8][4];
    #pragma unroll
    for (int nt = 0; nt < 8; nt++)
        #pragma unroll
        for (int c = 0; c < 4; c++) sacc[nt][c] = 0.f;
    #pragma unroll
    for (int kt = 0; kt < 2; kt++) {
        const int kb = kt * 16;
        const int r0 = 16 * w + lr;
        uint32_t ah[4], al[4];
        ah[0] = *(uint32_t*)&sQ[0][r0][kb + lc];
        ah[1] = *(uint32_t*)&sQ[0][r0 + 8][kb + lc];
        ah[2] = *(uint32_t*)&sQ[0][r0][kb + lc + 8];
        ah[3] = *(uint32_t*)&sQ[0][r0 + 8][kb + lc + 8];
        al[0] = *(uint32_t*)&sQ[1][r0][kb + lc];
        al[1] = *(uint32_t*)&sQ[1][r0 + 8][kb + lc];
        al[2] = *(uint32_t*)&sQ[1][r0][kb + lc + 8];
        al[3] = *(uint32_t*)&sQ[1][r0 + 8][kb + lc + 8];
        uint32_t bh[8][2], bl[8][2];
        #pragma unroll
        for (int nt = 0; nt < 8; nt++) {
            int rn = nt * 8 + lr;
            bh[nt][0] = *(uint32_t*)&sK[0][rn][kb + lc];
            bh[nt][1] = *(uint32_t*)&sK[0][rn][kb + lc + 8];
            bl[nt][0] = *(uint32_t*)&sK[1][rn][kb + lc];
            bl[nt][1] = *(uint32_t*)&sK[1][rn][kb + lc + 8];
        }
        #pragma unroll
        for (int nt = 0; nt < 8; nt++) mma16816(sacc[nt], ah, bh[nt]);
        #pragma unroll
        for (int nt = 0; nt < 8; nt++) mma16816(sacc[nt], ah, bl[nt]);
        #pragma unroll
        for (int nt = 0; nt < 8; nt++) mma16816(sacc[nt], al, bh[nt]);
    }

    // ---- bias add (fragment-order table; cols>=49 get -1e30) ----
    {
        const float4* bf = (const float4*)(g_biasfrag + ((head * 4 + w) * 32 + lane) * 32);
        #pragma unroll
        for (int nt = 0; nt < 8; nt++) {
            float4 bb = __ldg(&bf[nt]);
            sacc[nt][0] += bb.x; sacc[nt][1] += bb.y;
            sacc[nt][2] += bb.z; sacc[nt][3] += bb.w;
        }
    }

    // ---- softmax in registers (rows r0=16w+lr, r1=r0+8; quad shfl) ----
    {
        float mx0 = -3.0e38f, mx1 = -3.0e38f;
        #pragma unroll
        for (int nt = 0; nt < 8; nt++) {
            mx0 = fmaxf(mx0, fmaxf(sacc[nt][0], sacc[nt][1]));
            mx1 = fmaxf(mx1, fmaxf(sacc[nt][2], sacc[nt][3]));
        }
        mx0 = fmaxf(mx0, __shfl_xor_sync(0xffffffffu, mx0, 1));
        mx0 = fmaxf(mx0, __shfl_xor_sync(0xffffffffu, mx0, 2));
        mx1 = fmaxf(mx1, __shfl_xor_sync(0xffffffffu, mx1, 1));
        mx1 = fmaxf(mx1, __shfl_xor_sync(0xffffffffu, mx1, 2));
        float s0 = 0.f, s1 = 0.f;
        #pragma unroll
        for (int nt = 0; nt < 8; nt++) {
            sacc[nt][0] = __expf(sacc[nt][0] - mx0);
            sacc[nt][1] = __expf(sacc[nt][1] - mx0);
            sacc[nt][2] = __expf(sacc[nt][2] - mx1);
            sacc[nt][3] = __expf(sacc[nt][3] - mx1);
            s0 += sacc[nt][0] + sacc[nt][1];
            s1 += sacc[nt][2] + sacc[nt][3];
        }
        s0 += __shfl_xor_sync(0xffffffffu, s0, 1);
        s0 += __shfl_xor_sync(0xffffffffu, s0, 2);
        s1 += __shfl_xor_sync(0xffffffffu, s1, 1);
        s1 += __shfl_xor_sync(0xffffffffu, s1, 2);
        float i0 = __fdividef(1.f, s0), i1 = __fdividef(1.f, s1);
        #pragma unroll
        for (int nt = 0; nt < 8; nt++) {
            sacc[nt][0] *= i0; sacc[nt][1] *= i0;
            sacc[nt][2] *= i1; sacc[nt][3] *= i1;
        }
    }

    // ---- repack P d-frags -> a-frags (split h/l in registers) ----
    uint32_t pah[4][4], pal[4][4];
    #pragma unroll
    for (int jj = 0; jj < 4; jj++) {
        __nv_bfloat16 h[8], l[8];
        #pragma unroll
        for (int c = 0; c < 4; c++) {
            split_bf16(sacc[2 * jj][c], h[c], l[c]);
            split_bf16(sacc[2 * jj + 1][c], h[4 + c], l[4 + c]);
        }
        pah[jj][0] = pk2(h[0], h[1]);  pah[jj][1] = pk2(h[2], h[3]);
        pah[jj][2] = pk2(h[4], h[5]);  pah[jj][3] = pk2(h[6], h[7]);
        pal[jj][0] = pk2(l[0], l[1]);  pal[jj][1] = pk2(l[2], l[3]);
        pal[jj][2] = pk2(l[4], l[5]);  pal[jj][3] = pk2(l[6], l[7]);
    }

    // ---- O = P V (3-term): M=16/warp, N=32, K=64 ----
    float oacc[4][4];
    #pragma unroll
    for (int nt = 0; nt < 4; nt++)
        #pragma unroll
        for (int c = 0; c < 4; c++) oacc[nt][c] = 0.f;
    #pragma unroll
    for (int jj = 0; jj < 4; jj++) {
        const int kb = jj * 16;
        uint32_t bvh[4][2], bvl[4][2];
        #pragma unroll
        for (int nt = 0; nt < 4; nt++) {
            int rn = nt * 8 + lr;
            bvh[nt][0] = *(uint32_t*)&sV[0][rn][kb + lc];
            bvh[nt][1] = *(uint32_t*)&sV[0][rn][kb + lc + 8];
            bvl[nt][0] = *(uint32_t*)&sV[1][rn][kb + lc];
            bvl[nt][1] = *(uint32_t*)&sV[1][rn][kb + lc + 8];
        }
        #pragma unroll
        for (int nt = 0; nt < 4; nt++) mma16816(oacc[nt], pah[jj], bvh[nt]);
        #pragma unroll
        for (int nt = 0; nt < 4; nt++) mma16816(oacc[nt], pah[jj], bvl[nt]);
        #pragma unroll
        for (int nt = 0; nt < 4; nt++) mma16816(oacc[nt], pal[jj], bvh[nt]);
    }

    // ---- epilogue: write O h/l planes [t][c] ----
    {
        int r0 = 16 * w + lr;
        if (r0 < 49) {
            size_t t = (size_t)win * 49 + r0;
            #pragma unroll
            for (int nt = 0; nt < 4; nt++) {
                int c = head * 32 + nt * 8 + lc;
                __nv_bfloat16 h0, l0, h1, l1;
                split_bf16(oacc[nt][0], h0, l0);
                split_bf16(oacc[nt][1], h1, l1);
                g_ath32[t * 128 + (c >> 1)] = pk2(h0, h1);
                g_atl32[t * 128 + (c >> 1)] = pk2(l0, l1);
            }
        }
        int r1 = r0 + 8;
        if (r1 < 49) {
            size_t t = (size_t)win * 49 + r1;
            #pragma unroll
            for (int nt = 0; nt < 4; nt++) {
                int c = head * 32 + nt * 8 + lc;
                __nv_bfloat16 h0, l0, h1, l1;
                split_bf16(oacc[nt][2], h0, l0);
                split_bf16(oacc[nt][3], h1, l1);
                g_ath32[t * 128 + (c >> 1)] = pk2(h0, h1);
                g_atl32[t * 128 + (c >> 1)] = pk2(l0, l1);
            }
        }
    }
}

// ========================= k3: projection GEMM, cp.async + ldmatrix =========
__device__ __forceinline__ void k3_load_chunk(
    __nv_bfloat16* dsm, int buf, int cc, int tid, int t0, int n0g)
{
    const int kc = cc * 32;
    __nv_bfloat16* bb = dsm + buf * 4 * PL;
    #pragma unroll
    for (int i = 0; i < 4; i++) {
        int idx = tid + i * 256;
        int m = idx >> 3, sub = idx & 7, pl = sub >> 2, c4 = sub & 3;
        const __nv_bfloat16* base = (const __nv_bfloat16*)(pl ? g_atl32 : g_ath32);
        cp16(bb + pl * PL + m * KPAD + c4 * 8, base + (size_t)(t0 + m) * 256 + kc + c4 * 8);
    }
    #pragma unroll
    for (int i = 0; i < 4; i++) {
        int idx = tid + i * 256;
        int n = idx >> 3, sub = idx & 7, pl = sub >> 2, c4 = sub & 3;
        const __nv_bfloat16* src = (pl ? g_wprojT_l : g_wprojT_h) + (size_t)(n0g + n) * 256 + kc + c4 * 8;
        cp16(bb + (2 + pl) * PL + n * KPAD + c4 * 8, src);
    }
    CP_COMMIT();
}

__global__ __launch_bounds__(256, 2) void k3_proj_mma(
    const float* __restrict__ bias, float* __restrict__ out)
{
    extern __shared__ __nv_bfloat16 dsm[];
    __shared__ int boff[128];
    const int tid = threadIdx.x;
    const int wid = tid >> 5, lane = tid & 31;
    const int wm = wid >> 2, wn = wid & 3;
    const int lr = lane >> 2, lc = (lane & 3) * 2;
    const int t0 = blockIdx.x * 128;
    const int n0g = blockIdx.y * 128;

    if (tid < 128) {
        int t = t0 + tid;
        int win = t / 49, n = t - win * 49;
        int b = win >> 8, rem = win & 255;
        boff[tid] = b * (256 * HWD) + ((rem >> 4) * 7 + n / 7) * 112 + (rem & 15) * 7 + n % 7;
    }
    float acc[4][4][4];
    #pragma unroll
    for (int mt = 0; mt < 4; mt++)
        #pragma unroll
        for (int nt = 0; nt < 4; nt++)
            #pragma unroll
            for (int r = 0; r < 4; r++) acc[mt][nt][r] = 0.f;

    k3_load_chunk(dsm, 0, 0, tid, t0, n0g);
    for (int cc = 0; cc < 8; cc++) {
        if (cc < 7) { k3_load_chunk(dsm, (cc + 1) & 1, cc + 1, tid, t0, n0g); CP_WAIT1(); }
        else CP_WAIT0();
        __syncthreads();
        const __nv_bfloat16* bb = dsm + (cc & 1) * 4 * PL;
        GEMM_KSTEP(bb, bb + PL, bb + 2 * PL, bb + 3 * PL, 0);
        GEMM_KSTEP(bb, bb + PL, bb + 2 * PL, bb + 3 * PL, 16);
        __syncthreads();
    }

    #pragma unroll
    for (int nt = 0; nt < 4; nt++) {
        int c = n0g + wn * 32 + nt * 8 + lc;
        float bb0 = __ldg(&bias[c]);
        float bb1 = __ldg(&bias[c + 1]);
        #pragma unroll
        for (int mt = 0; mt < 4; mt++) {
            #pragma unroll
            for (int hf = 0; hf < 2; hf++) {
                int bo = boff[wm * 64 + mt * 16 + lr + hf * 8];
                out[bo + (size_t)c * HWD]       = acc[mt][nt][hf * 2 + 0] + bb0;
                out[bo + (size_t)(c + 1) * HWD] = acc[mt][nt][hf * 2 + 1] + bb1;
            }
        }
    }
}

// ---------------------------------------------------------------------------
extern "C" void kernel_launch(void* const* d_in, const int* in_sizes, int n_in,
                              void* d_out, int out_size)
{
    const float* x      = (const float*)d_in[0];
    const float* w_qkv  = (const float*)d_in[1];
    const float* b_qkv  = (const float*)d_in[2];
    const float* w_proj = (const float*)d_in[3];
    const float* b_proj = (const float*)d_in[4];
    const float* rpb    = (const float*)d_in[5];
    float* out = (float*)d_out;

    cudaFuncSetAttribute(k1_qkv_mma, cudaFuncAttributeMaxDynamicSharedMemorySize, SMEM_DYN);
    cudaFuncSetAttribute(k3_proj_mma, cudaFuncAttributeMaxDynamicSharedMemorySize, SMEM_DYN);

    k0_wqkv<<<768, 256>>>(w_qkv);
    k0_wproj<<<256, 256>>>(w_proj);
    k0b<<<128, 256>>>(rpb);
    k0x<<<3136, 256>>>(x);
    k1_qkv_mma<<<dim3(784, 6), 256, SMEM_DYN>>>(b_qkv);
    k2_attn<<<16384, 128>>>();
    k3_proj_mma<<<dim3(784, 2), 256, SMEM_DYN>>>(b_proj, out);
}

// round 15
// speedup vs baseline: 1.1205x; 1.0881x over previous
#include <cuda_runtime.h>
#include <cuda_bf16.h>
#include <cstdint>

#define HWD 12544        // 112*112
#define TOKS 100352      // 2048 windows * 49
#define NWH  16384       // 2048 windows * 8 heads
#define QSCALE 0.17677669529663687f   // 32^-0.5

// ========================= device scratch ===================================
__device__ __nv_bfloat16 g_xh[(size_t)TOKS * 256];   // x gathered [t][c], high
__device__ __nv_bfloat16 g_xl[(size_t)TOKS * 256];   // low
__device__ uint32_t g_ath32[(size_t)TOKS * 128];     // attn out [t][c] bf16 pairs, high
__device__ uint32_t g_atl32[(size_t)TOKS * 128];     // low
__device__ uint32_t g_qh[(size_t)NWH * 784];         // q [wh][tok][d] bf16 pairs
__device__ uint32_t g_ql[(size_t)NWH * 784];
__device__ uint32_t g_kh[(size_t)NWH * 784];
__device__ uint32_t g_kl[(size_t)NWH * 784];
__device__ uint32_t g_vh32[(size_t)NWH * 784];       // v [wh][tok][d] bf16 pairs
__device__ uint32_t g_vl32[(size_t)NWH * 784];
__device__ float g_biasfrag[8 * 4096];               // rpb bias in d-frag order per head
__device__ __nv_bfloat16 g_wqkvT_h[768 * 256];       // [n][k]
__device__ __nv_bfloat16 g_wqkvT_l[768 * 256];
__device__ __nv_bfloat16 g_wprojT_h[256 * 256];
__device__ __nv_bfloat16 g_wprojT_l[256 * 256];

__device__ __forceinline__ void split_bf16(float v, __nv_bfloat16& h, __nv_bfloat16& l) {
    h = __float2bfloat16(v);
    l = __float2bfloat16(v - __bfloat162float(h));
}
__device__ __forceinline__ uint32_t pk2(__nv_bfloat16 a, __nv_bfloat16 b) {
    __nv_bfloat162 t; t.x = a; t.y = b;
    return *(uint32_t*)&t;
}

// mma.sync m16n8k16 bf16 (base ISA, sm_80+)
__device__ __forceinline__ void mma16816(
    float* d, const uint32_t* a, const uint32_t* b)
{
    asm volatile(
        "mma.sync.aligned.m16n8k16.row.col.f32.bf16.bf16.f32 "
        "{%0,%1,%2,%3}, {%4,%5,%6,%7}, {%8,%9}, {%0,%1,%2,%3};"
        : "+f"(d[0]), "+f"(d[1]), "+f"(d[2]), "+f"(d[3])
        : "r"(a[0]), "r"(a[1]), "r"(a[2]), "r"(a[3]), "r"(b[0]), "r"(b[1]));
}

__device__ __forceinline__ void ldsm4(uint32_t* r, const void* p) {
    uint32_t a = (uint32_t)__cvta_generic_to_shared(p);
    asm volatile("ldmatrix.sync.aligned.m8n8.x4.shared.b16 {%0,%1,%2,%3}, [%4];"
                 : "=r"(r[0]), "=r"(r[1]), "=r"(r[2]), "=r"(r[3]) : "r"(a));
}

__device__ __forceinline__ void cp16(void* dst, const void* src) {
    uint32_t d = (uint32_t)__cvta_generic_to_shared(dst);
    asm volatile("cp.async.ca.shared.global [%0], [%1], 16;" :: "r"(d), "l"(src));
}
#define CP_COMMIT() asm volatile("cp.async.commit_group;" ::: "memory")
#define CP_WAIT1()  asm volatile("cp.async.wait_group 1;" ::: "memory")
#define CP_WAIT0()  asm volatile("cp.async.wait_group 0;" ::: "memory")

#define KPAD 40            // bf16 per smem row; 80B stride, conflict-free
#define PL (128 * KPAD)    // plane elems
#define SMEM_DYN (2 * 4 * PL * 2)   // 81920 B

// ========================= k0: weight transpose + split =====================
__global__ void k0_wqkv(const float* __restrict__ w) {
    int idx = blockIdx.x * 256 + threadIdx.x;
    int k = idx / 768, n = idx % 768;
    __nv_bfloat16 h, l; split_bf16(w[idx], h, l);
    g_wqkvT_h[n * 256 + k] = h;
    g_wqkvT_l[n * 256 + k] = l;
}
__global__ void k0_wproj(const float* __restrict__ w) {
    int idx = blockIdx.x * 256 + threadIdx.x;
    int k = idx >> 8, n = idx & 255;
    __nv_bfloat16 h, l; split_bf16(w[idx], h, l);
    g_wprojT_h[n * 256 + k] = h;
    g_wprojT_l[n * 256 + k] = l;
}

// ========================= k0b: rel-pos bias in fragment order ==============
__global__ void k0b(const float* __restrict__ rpb) {
    int idx = blockIdx.x * 256 + threadIdx.x;   // < 32768
    int head = idx >> 12, e = idx & 4095;
    int w = e >> 10, r = e & 1023;
    int lane = r >> 5, v = r & 31;
    int nt = v >> 2, cc = v & 3;
    int row = 16 * w + (lane >> 2) + ((cc >= 2) ? 8 : 0);
    int col = nt * 8 + (lane & 3) * 2 + (cc & 1);
    float val;
    if (col >= 49) val = -1e30f;
    else if (row >= 49) val = 0.f;
    else {
        int in_ = row / 7, jn = row % 7, im = col / 7, jm = col % 7;
        int ri = (in_ - im + 6) * 13 + (jn - jm + 6);
        val = rpb[ri * 8 + head];
    }
    g_biasfrag[idx] = val;
}

// ========================= k0x: gather + split x -> [t][c] h/l planes =======
__global__ __launch_bounds__(256) void k0x(const float* __restrict__ x)
{
    __shared__ __nv_bfloat16 sh[32 * 266], sl[32 * 266];
    __shared__ int boff[32];
    const int tid = threadIdx.x;
    const int t0 = blockIdx.x * 32;
    if (tid < 32) {
        int t = t0 + tid;
        int win = t / 49, n = t - win * 49;
        int b = win >> 8, rem = win & 255;
        boff[tid] = b * (256 * HWD) + ((rem >> 4) * 7 + n / 7) * 112 + (rem & 15) * 7 + n % 7;
    }
    __syncthreads();
    {
        int t = tid & 31, c0 = tid >> 5;
        int bo = boff[t];
        #pragma unroll
        for (int it = 0; it < 32; it++) {
            int c = c0 + it * 8;
            float v = __ldg(&x[(size_t)bo + (size_t)c * HWD]);
            __nv_bfloat16 h, l; split_bf16(v, h, l);
            sh[t * 266 + c] = h;
            sl[t * 266 + c] = l;
        }
    }
    __syncthreads();
    #pragma unroll
    for (int i = 0; i < 16; i++) {
        int idx = tid + i * 256;
        int tt = idx >> 7, cp2 = idx & 127;
        uint32_t hv = *(uint32_t*)&sh[tt * 266 + cp2 * 2];
        uint32_t lv = *(uint32_t*)&sl[tt * 266 + cp2 * 2];
        *(uint32_t*)&g_xh[(size_t)(t0 + tt) * 256 + cp2 * 2] = hv;
        *(uint32_t*)&g_xl[(size_t)(t0 + tt) * 256 + cp2 * 2] = lv;
    }
}

// ========================= shared GEMM mainloop core ========================
#define GEMM_KSTEP(Ah, Al, Bh, Bl, kb)                                          \
    do {                                                                        \
        uint32_t bfh[2][4], bfl[2][4];                                          \
        int brow = (lane & 7) + ((lane >> 3) & 1) * 8;                          \
        int bk = (kb) + (lane >> 4) * 8;                                        \
        _Pragma("unroll")                                                       \
        for (int p = 0; p < 2; p++) {                                           \
            ldsm4(bfh[p], &(Bh)[(wn * 32 + p * 16 + brow) * KPAD + bk]);        \
            ldsm4(bfl[p], &(Bl)[(wn * 32 + p * 16 + brow) * KPAD + bk]);        \
        }                                                                       \
        int arow = lane & 15;                                                   \
        _Pragma("unroll")                                                       \
        for (int mt = 0; mt < 4; mt++) {                                        \
            uint32_t ah[4], al[4];                                              \
            ldsm4(ah, &(Ah)[(wm * 64 + mt * 16 + arow) * KPAD + bk]);           \
            ldsm4(al, &(Al)[(wm * 64 + mt * 16 + arow) * KPAD + bk]);           \
            _Pragma("unroll")                                                   \
            for (int nt = 0; nt < 4; nt++) {                                    \
                uint32_t bb[2] = { bfh[nt >> 1][nt & 1], bfh[nt >> 1][(nt & 1) + 2] }; \
                mma16816(acc[mt][nt], ah, bb);                                  \
            }                                                                   \
            _Pragma("unroll")                                                   \
            for (int nt = 0; nt < 4; nt++) {                                    \
                uint32_t bb[2] = { bfl[nt >> 1][nt & 1], bfl[nt >> 1][(nt & 1) + 2] }; \
                mma16816(acc[mt][nt], ah, bb);                                  \
            }                                                                   \
            _Pragma("unroll")                                                   \
            for (int nt = 0; nt < 4; nt++) {                                    \
                uint32_t bb[2] = { bfh[nt >> 1][nt & 1], bfh[nt >> 1][(nt & 1) + 2] }; \
                mma16816(acc[mt][nt], al, bb);                                  \
            }                                                                   \
        }                                                                       \
    } while (0)

// ========================= k1: QKV GEMM, cp.async + ldmatrix ================
// grid (6, 784): consecutive CTAs share the same A token-tile -> L2 reuse.
__device__ __forceinline__ void k1_load_chunk(
    __nv_bfloat16* dsm, int buf, int cc, int tid, int t0, int n0g)
{
    const int kc = cc * 32;
    __nv_bfloat16* bb = dsm + buf * 4 * PL;
    #pragma unroll
    for (int i = 0; i < 4; i++) {
        int idx = tid + i * 256;
        int m = idx >> 3, sub = idx & 7, pl = sub >> 2, c4 = sub & 3;
        const __nv_bfloat16* src = (pl ? g_xl : g_xh) + (size_t)(t0 + m) * 256 + kc + c4 * 8;
        cp16(bb + pl * PL + m * KPAD + c4 * 8, src);
    }
    #pragma unroll
    for (int i = 0; i < 4; i++) {
        int idx = tid + i * 256;
        int n = idx >> 3, sub = idx & 7, pl = sub >> 2, c4 = sub & 3;
        const __nv_bfloat16* src = (pl ? g_wqkvT_l : g_wqkvT_h) + (size_t)(n0g + n) * 256 + kc + c4 * 8;
        cp16(bb + (2 + pl) * PL + n * KPAD + c4 * 8, src);
    }
    CP_COMMIT();
}

__global__ __launch_bounds__(256, 2) void k1_qkv_mma(const float* __restrict__ bias)
{
    extern __shared__ __nv_bfloat16 dsm[];
    const int tid = threadIdx.x;
    const int wid = tid >> 5, lane = tid & 31;
    const int wm = wid >> 2, wn = wid & 3;
    const int lr = lane >> 2, lc = (lane & 3) * 2;
    const int t0 = blockIdx.y * 128;
    const int n0g = blockIdx.x * 128;

    float acc[4][4][4];
    #pragma unroll
    for (int mt = 0; mt < 4; mt++)
        #pragma unroll
        for (int nt = 0; nt < 4; nt++)
            #pragma unroll
            for (int r = 0; r < 4; r++) acc[mt][nt][r] = 0.f;

    k1_load_chunk(dsm, 0, 0, tid, t0, n0g);
    for (int cc = 0; cc < 8; cc++) {
        if (cc < 7) { k1_load_chunk(dsm, (cc + 1) & 1, cc + 1, tid, t0, n0g); CP_WAIT1(); }
        else CP_WAIT0();
        __syncthreads();
        const __nv_bfloat16* bb = dsm + (cc & 1) * 4 * PL;
        GEMM_KSTEP(bb, bb + PL, bb + 2 * PL, bb + 3 * PL, 0);
        GEMM_KSTEP(bb, bb + PL, bb + 2 * PL, bb + 3 * PL, 16);
        __syncthreads();
    }

    // Epilogue: branch-free u32 pair stores, layout [wh][tok][d] for q,k,v.
    {
        int col0 = n0g + wn * 32;
        int which = col0 >> 8;
        int head = (col0 >> 5) & 7;
        float scl = (which == 0) ? QSCALE : 1.f;
        uint32_t* dh = (which == 0) ? g_qh : (which == 1) ? g_kh : g_vh32;
        uint32_t* dl = (which == 0) ? g_ql : (which == 1) ? g_kl : g_vl32;
        #pragma unroll
        for (int nt = 0; nt < 4; nt++) {
            int dloc = nt * 8 + lc;
            float bb0 = __ldg(&bias[col0 + dloc]);
            float bb1 = __ldg(&bias[col0 + dloc + 1]);
            #pragma unroll
            for (int mt = 0; mt < 4; mt++) {
                #pragma unroll
                for (int hf = 0; hf < 2; hf++) {
                    int t = t0 + wm * 64 + mt * 16 + lr + hf * 8;
                    int win = t / 49, n = t - win * 49;
                    int wh = win * 8 + head;
                    float vx = (acc[mt][nt][hf * 2 + 0] + bb0) * scl;
                    float vy = (acc[mt][nt][hf * 2 + 1] + bb1) * scl;
                    __nv_bfloat16 hx, lx, hy, ly;
                    split_bf16(vx, hx, lx);
                    split_bf16(vy, hy, ly);
                    uint32_t off = (uint32_t)wh * 784 + n * 16 + (dloc >> 1);
                    dh[off] = pk2(hx, hy);
                    dl[off] = pk2(lx, ly);
                }
            }
        }
    }
}

// ========================= k2: attention via mma.sync =======================
__global__ __launch_bounds__(128) void k2_attn()
{
    __shared__ __nv_bfloat16 sQ[2][64][40];   // [plane][tok][d]
    __shared__ __nv_bfloat16 sK[2][64][40];   // [plane][tok][d]
    __shared__ __nv_bfloat16 sV[2][32][72];   // [plane][d][tok] (transposed at load)
    const int tid = threadIdx.x;
    const int wh = blockIdx.x;
    const int head = wh & 7, win = wh >> 3;
    const int w = tid >> 5, lane = tid & 31;
    const int lr = lane >> 2, lc = (lane & 3) * 2;

    // zero smem (pads MUST be 0)
    {
        uint32_t* z1 = (uint32_t*)&sQ[0][0][0];
        uint32_t* z2 = (uint32_t*)&sK[0][0][0];
        uint32_t* z3 = (uint32_t*)&sV[0][0][0];
        for (int i = tid; i < 2560; i += 128) { z1[i] = 0; z2[i] = 0; }
        for (int i = tid; i < 1152; i += 128) z3[i] = 0;
    }
    __syncthreads();

    // load q,k,v (u32 pairs, coalesced); v transposed into [d][tok] smem
    {
        const uint32_t* pq0 = g_qh + (size_t)wh * 784;
        const uint32_t* pq1 = g_ql + (size_t)wh * 784;
        const uint32_t* pk0 = g_kh + (size_t)wh * 784;
        const uint32_t* pk1 = g_kl + (size_t)wh * 784;
        const uint32_t* pv0 = g_vh32 + (size_t)wh * 784;
        const uint32_t* pv1 = g_vl32 + (size_t)wh * 784;
        for (int i = tid; i < 784; i += 128) {
            int row = i >> 4, p = i & 15;
            *(uint32_t*)&sQ[0][row][p * 2] = __ldg(&pq0[i]);
            *(uint32_t*)&sQ[1][row][p * 2] = __ldg(&pq1[i]);
            *(uint32_t*)&sK[0][row][p * 2] = __ldg(&pk0[i]);
            *(uint32_t*)&sK[1][row][p * 2] = __ldg(&pk1[i]);
            uint32_t v0 = __ldg(&pv0[i]);
            uint32_t v1 = __ldg(&pv1[i]);
            __nv_bfloat162 b0 = *(__nv_bfloat162*)&v0;
            __nv_bfloat162 b1 = *(__nv_bfloat162*)&v1;
            sV[0][2 * p][row] = b0.x;
            sV[0][2 * p + 1][row] = b0.y;
            sV[1][2 * p][row] = b1.x;
            sV[1][2 * p + 1][row] = b1.y;
        }
    }
    __syncthreads();

    // ---- S = q k^T (3-term): M=16/warp, N=64, K=32 ----
    float sacc[8][4];
    #pragma unroll
    for (int nt = 0; nt < 8; nt++)
        #pragma unroll
        for (int c = 0; c < 4; c++) sacc[nt][c] = 0.f;
    #pragma unroll
    for (int kt = 0; kt < 2; kt++) {
        const int kb = kt * 16;
        const int r0 = 16 * w + lr;
        uint32_t ah[4], al[4];
        ah[0] = *(uint32_t*)&sQ[0][r0][kb + lc];
        ah[1] = *(uint32_t*)&sQ[0][r0 + 8][kb + lc];
        ah[2] = *(uint32_t*)&sQ[0][r0][kb + lc + 8];
        ah[3] = *(uint32_t*)&sQ[0][r0 + 8][kb + lc + 8];
        al[0] = *(uint32_t*)&sQ[1][r0][kb + lc];
        al[1] = *(uint32_t*)&sQ[1][r0 + 8][kb + lc];
        al[2] = *(uint32_t*)&sQ[1][r0][kb + lc + 8];
        al[3] = *(uint32_t*)&sQ[1][r0 + 8][kb + lc + 8];
        uint32_t bh[8][2], bl[8][2];
        #pragma unroll
        for (int nt = 0; nt < 8; nt++) {
            int rn = nt * 8 + lr;
            bh[nt][0] = *(uint32_t*)&sK[0][rn][kb + lc];
            bh[nt][1] = *(uint32_t*)&sK[0][rn][kb + lc + 8];
            bl[nt][0] = *(uint32_t*)&sK[1][rn][kb + lc];
            bl[nt][1] = *(uint32_t*)&sK[1][rn][kb + lc + 8];
        }
        #pragma unroll
        for (int nt = 0; nt < 8; nt++) mma16816(sacc[nt], ah, bh[nt]);
        #pragma unroll
        for (int nt = 0; nt < 8; nt++) mma16816(sacc[nt], ah, bl[nt]);
        #pragma unroll
        for (int nt = 0; nt < 8; nt++) mma16816(sacc[nt], al, bh[nt]);
    }

    // ---- bias add ----
    {
        const float4* bf = (const float4*)(g_biasfrag + ((head * 4 + w) * 32 + lane) * 32);
        #pragma unroll
        for (int nt = 0; nt < 8; nt++) {
            float4 bb = __ldg(&bf[nt]);
            sacc[nt][0] += bb.x; sacc[nt][1] += bb.y;
            sacc[nt][2] += bb.z; sacc[nt][3] += bb.w;
        }
    }

    // ---- softmax in registers (quad shfl) ----
    {
        float mx0 = -3.0e38f, mx1 = -3.0e38f;
        #pragma unroll
        for (int nt = 0; nt < 8; nt++) {
            mx0 = fmaxf(mx0, fmaxf(sacc[nt][0], sacc[nt][1]));
            mx1 = fmaxf(mx1, fmaxf(sacc[nt][2], sacc[nt][3]));
        }
        mx0 = fmaxf(mx0, __shfl_xor_sync(0xffffffffu, mx0, 1));
        mx0 = fmaxf(mx0, __shfl_xor_sync(0xffffffffu, mx0, 2));
        mx1 = fmaxf(mx1, __shfl_xor_sync(0xffffffffu, mx1, 1));
        mx1 = fmaxf(mx1, __shfl_xor_sync(0xffffffffu, mx1, 2));
        float s0 = 0.f, s1 = 0.f;
        #pragma unroll
        for (int nt = 0; nt < 8; nt++) {
            sacc[nt][0] = __expf(sacc[nt][0] - mx0);
            sacc[nt][1] = __expf(sacc[nt][1] - mx0);
            sacc[nt][2] = __expf(sacc[nt][2] - mx1);
            sacc[nt][3] = __expf(sacc[nt][3] - mx1);
            s0 += sacc[nt][0] + sacc[nt][1];
            s1 += sacc[nt][2] + sacc[nt][3];
        }
        s0 += __shfl_xor_sync(0xffffffffu, s0, 1);
        s0 += __shfl_xor_sync(0xffffffffu, s0, 2);
        s1 += __shfl_xor_sync(0xffffffffu, s1, 1);
        s1 += __shfl_xor_sync(0xffffffffu, s1, 2);
        float i0 = __fdividef(1.f, s0), i1 = __fdividef(1.f, s1);
        #pragma unroll
        for (int nt = 0; nt < 8; nt++) {
            sacc[nt][0] *= i0; sacc[nt][1] *= i0;
            sacc[nt][2] *= i1; sacc[nt][3] *= i1;
        }
    }

    // ---- repack P d-frags -> a-frags (split h/l in registers) ----
    uint32_t pah[4][4], pal[4][4];
    #pragma unroll
    for (int jj = 0; jj < 4; jj++) {
        __nv_bfloat16 h[8], l[8];
        #pragma unroll
        for (int c = 0; c < 4; c++) {
            split_bf16(sacc[2 * jj][c], h[c], l[c]);
            split_bf16(sacc[2 * jj + 1][c], h[4 + c], l[4 + c]);
        }
        pah[jj][0] = pk2(h[0], h[1]);  pah[jj][1] = pk2(h[2], h[3]);
        pah[jj][2] = pk2(h[4], h[5]);  pah[jj][3] = pk2(h[6], h[7]);
        pal[jj][0] = pk2(l[0], l[1]);  pal[jj][1] = pk2(l[2], l[3]);
        pal[jj][2] = pk2(l[4], l[5]);  pal[jj][3] = pk2(l[6], l[7]);
    }

    // ---- O = P V (3-term): M=16/warp, N=32, K=64 ----
    float oacc[4][4];
    #pragma unroll
    for (int nt = 0; nt < 4; nt++)
        #pragma unroll
        for (int c = 0; c < 4; c++) oacc[nt][c] = 0.f;
    #pragma unroll
    for (int jj = 0; jj < 4; jj++) {
        const int kb = jj * 16;
        uint32_t bvh[4][2], bvl[4][2];
        #pragma unroll
        for (int nt = 0; nt < 4; nt++) {
            int rn = nt * 8 + lr;
            bvh[nt][0] = *(uint32_t*)&sV[0][rn][kb + lc];
            bvh[nt][1] = *(uint32_t*)&sV[0][rn][kb + lc + 8];
            bvl[nt][0] = *(uint32_t*)&sV[1][rn][kb + lc];
            bvl[nt][1] = *(uint32_t*)&sV[1][rn][kb + lc + 8];
        }
        #pragma unroll
        for (int nt = 0; nt < 4; nt++) mma16816(oacc[nt], pah[jj], bvh[nt]);
        #pragma unroll
        for (int nt = 0; nt < 4; nt++) mma16816(oacc[nt], pah[jj], bvl[nt]);
        #pragma unroll
        for (int nt = 0; nt < 4; nt++) mma16816(oacc[nt], pal[jj], bvh[nt]);
    }

    // ---- epilogue: write O h/l planes [t][c] ----
    {
        int r0 = 16 * w + lr;
        if (r0 < 49) {
            size_t t = (size_t)win * 49 + r0;
            #pragma unroll
            for (int nt = 0; nt < 4; nt++) {
                int c = head * 32 + nt * 8 + lc;
                __nv_bfloat16 h0, l0, h1, l1;
                split_bf16(oacc[nt][0], h0, l0);
                split_bf16(oacc[nt][1], h1, l1);
                g_ath32[t * 128 + (c >> 1)] = pk2(h0, h1);
                g_atl32[t * 128 + (c >> 1)] = pk2(l0, l1);
            }
        }
        int r1 = r0 + 8;
        if (r1 < 49) {
            size_t t = (size_t)win * 49 + r1;
            #pragma unroll
            for (int nt = 0; nt < 4; nt++) {
                int c = head * 32 + nt * 8 + lc;
                __nv_bfloat16 h0, l0, h1, l1;
                split_bf16(oacc[nt][2], h0, l0);
                split_bf16(oacc[nt][3], h1, l1);
                g_ath32[t * 128 + (c >> 1)] = pk2(h0, h1);
                g_atl32[t * 128 + (c >> 1)] = pk2(l0, l1);
            }
        }
    }
}

// ========================= k3: projection GEMM, cp.async + ldmatrix =========
// grid (2, 784): consecutive CTAs share A token-tile -> L2 reuse.
__device__ __forceinline__ void k3_load_chunk(
    __nv_bfloat16* dsm, int buf, int cc, int tid, int t0, int n0g)
{
    const int kc = cc * 32;
    __nv_bfloat16* bb = dsm + buf * 4 * PL;
    #pragma unroll
    for (int i = 0; i < 4; i++) {
        int idx = tid + i * 256;
        int m = idx >> 3, sub = idx & 7, pl = sub >> 2, c4 = sub & 3;
        const __nv_bfloat16* base = (const __nv_bfloat16*)(pl ? g_atl32 : g_ath32);
        cp16(bb + pl * PL + m * KPAD + c4 * 8, base + (size_t)(t0 + m) * 256 + kc + c4 * 8);
    }
    #pragma unroll
    for (int i = 0; i < 4; i++) {
        int idx = tid + i * 256;
        int n = idx >> 3, sub = idx & 7, pl = sub >> 2, c4 = sub & 3;
        const __nv_bfloat16* src = (pl ? g_wprojT_l : g_wprojT_h) + (size_t)(n0g + n) * 256 + kc + c4 * 8;
        cp16(bb + (2 + pl) * PL + n * KPAD + c4 * 8, src);
    }
    CP_COMMIT();
}

__global__ __launch_bounds__(256, 2) void k3_proj_mma(
    const float* __restrict__ bias, float* __restrict__ out)
{
    extern __shared__ __nv_bfloat16 dsm[];
    __shared__ int boff[128];
    const int tid = threadIdx.x;
    const int wid = tid >> 5, lane = tid & 31;
    const int wm = wid >> 2, wn = wid & 3;
    const int lr = lane >> 2, lc = (lane & 3) * 2;
    const int t0 = blockIdx.y * 128;
    const int n0g = blockIdx.x * 128;

    if (tid < 128) {
        int t = t0 + tid;
        int win = t / 49, n = t - win * 49;
        int b = win >> 8, rem = win & 255;
        boff[tid] = b * (256 * HWD) + ((rem >> 4) * 7 + n / 7) * 112 + (rem & 15) * 7 + n % 7;
    }
    float acc[4][4][4];
    #pragma unroll
    for (int mt = 0; mt < 4; mt++)
        #pragma unroll
        for (int nt = 0; nt < 4; nt++)
            #pragma unroll
            for (int r = 0; r < 4; r++) acc[mt][nt][r] = 0.f;

    k3_load_chunk(dsm, 0, 0, tid, t0, n0g);
    for (int cc = 0; cc < 8; cc++) {
        if (cc < 7) { k3_load_chunk(dsm, (cc + 1) & 1, cc + 1, tid, t0, n0g); CP_WAIT1(); }
        else CP_WAIT0();
        __syncthreads();
        const __nv_bfloat16* bb = dsm + (cc & 1) * 4 * PL;
        GEMM_KSTEP(bb, bb + PL, bb + 2 * PL, bb + 3 * PL, 0);
        GEMM_KSTEP(bb, bb + PL, bb + 2 * PL, bb + 3 * PL, 16);
        __syncthreads();
    }

    #pragma unroll
    for (int nt = 0; nt < 4; nt++) {
        int c = n0g + wn * 32 + nt * 8 + lc;
        float bb0 = __ldg(&bias[c]);
        float bb1 = __ldg(&bias[c + 1]);
        #pragma unroll
        for (int mt = 0; mt < 4; mt++) {
            #pragma unroll
            for (int hf = 0; hf < 2; hf++) {
                int bo = boff[wm * 64 + mt * 16 + lr + hf * 8];
                out[bo + (size_t)c * HWD]       = acc[mt][nt][hf * 2 + 0] + bb0;
                out[bo + (size_t)(c + 1) * HWD] = acc[mt][nt][hf * 2 + 1] + bb1;
            }
        }
    }
}

// ---------------------------------------------------------------------------
extern "C" void kernel_launch(void* const* d_in, const int* in_sizes, int n_in,
                              void* d_out, int out_size)
{
    const float* x      = (const float*)d_in[0];
    const float* w_qkv  = (const float*)d_in[1];
    const float* b_qkv  = (const float*)d_in[2];
    const float* w_proj = (const float*)d_in[3];
    const float* b_proj = (const float*)d_in[4];
    const float* rpb    = (const float*)d_in[5];
    float* out = (float*)d_out;

    cudaFuncSetAttribute(k1_qkv_mma, cudaFuncAttributeMaxDynamicSharedMemorySize, SMEM_DYN);
    cudaFuncSetAttribute(k3_proj_mma, cudaFuncAttributeMaxDynamicSharedMemorySize, SMEM_DYN);

    k0_wqkv<<<768, 256>>>(w_qkv);
    k0_wproj<<<256, 256>>>(w_proj);
    k0b<<<128, 256>>>(rpb);
    k0x<<<3136, 256>>>(x);
    k1_qkv_mma<<<dim3(6, 784), 256, SMEM_DYN>>>(b_qkv);
    k2_attn<<<16384, 128>>>();
    k3_proj_mma<<<dim3(2, 784), 256, SMEM_DYN>>>(b_proj, out);
}